// round 7
// baseline (speedup 1.0000x reference)
#include <cuda_runtime.h>

#define ATT_H 128
#define KVH   256
#define NB    2
#define NS    1024
#define NQ    512
#define NROWS (NB*NS + NB*NQ)   // 3072 projection rows

// scratch (no allocations allowed)
__device__ float g_proj_kv[NB*NS*ATT_H];   // (B*S, 128)
__device__ float g_proj_q [NB*NQ*ATT_H];   // (B*SQ, 128)
__device__ float g_pp     [4*NROWS*ATT_H]; // proj k-split partials (x4)

__device__ __forceinline__ float fast_tanh(float x){ float y; asm("tanh.approx.f32 %0, %1;" : "=f"(y) : "f"(x)); return y; }
__device__ __forceinline__ float fast_ex2 (float x){ float y; asm("ex2.approx.f32 %0, %1;"  : "=f"(y) : "f"(x)); return y; }

__device__ __forceinline__ float2 ffma2(float2 a, float2 b, float2 c) {
    float2 d;
    asm("fma.rn.f32x2 %0, %1, %2, %3;"
        : "=l"(reinterpret_cast<unsigned long long&>(d))
        : "l"(reinterpret_cast<unsigned long long&>(a)),
          "l"(reinterpret_cast<unsigned long long&>(b)),
          "l"(reinterpret_cast<unsigned long long&>(c)));
    return d;
}

__device__ __forceinline__ void cp16(void* dst, const void* src) {
    unsigned d = (unsigned)__cvta_generic_to_shared(dst);
    asm volatile("cp.async.cg.shared.global [%0], [%1], 16;" :: "r"(d), "l"(src));
}
__device__ __forceinline__ void cp_commit() { asm volatile("cp.async.commit_group;"); }
__device__ __forceinline__ void cp_wait0()  { asm volatile("cp.async.wait_group 0;" ::: "memory"); }

// ---------------- Kernel 1: proj partials, k-split x4 ----------------
// Block: 32 rows x 64 cols x 64 k, 128 threads, thread tile 4x4. Grid 768.
__global__ void __launch_bounds__(128) proj_kernel(
    const float* __restrict__ kv, const float* __restrict__ qy,
    const float* __restrict__ Wkv, const float* __restrict__ Wq)
{
    __shared__ float w_sh [64*64];
    __shared__ float in_T [64*34];

    const int tid = threadIdx.x;
    const int rb  = blockIdx.x;       // 768 = 96 rowblk * 2 ch * 4 kh
    const int kh  = rb & 3;
    const int ch  = (rb >> 2) & 1;
    const int row0g = (rb >> 3) * 32;

    const float *in, *W;
    if (row0g < NB*NS) { in = kv + (size_t)row0g*256;           W = Wkv; }
    else               { in = qy + (size_t)(row0g - NB*NS)*256; W = Wq;  }
    in += kh*64;
    W  += (size_t)kh*64*128;

    const int tx = tid & 15;
    const int ty = tid >> 4;

    // load W tile 64k x 64c and input tile 32r x 64k (transposed)
    #pragma unroll
    for (int j = 0; j < 8; j++) {
        int f4 = tid + 128*j; int kk = f4 >> 4, c4 = f4 & 15;
        ((float4*)w_sh)[kk*16 + c4] = *(const float4*)(W + (size_t)kk*128 + ch*64 + c4*4);
    }
    #pragma unroll
    for (int j = 0; j < 4; j++) {
        int f4 = tid + 128*j; int r = f4 >> 4, k4 = f4 & 15;
        float4 v = *(const float4*)(in + (size_t)r*256 + k4*4);
        in_T[(k4*4+0)*34 + r] = v.x;
        in_T[(k4*4+1)*34 + r] = v.y;
        in_T[(k4*4+2)*34 + r] = v.z;
        in_T[(k4*4+3)*34 + r] = v.w;
    }
    __syncthreads();

    float2 acc[4][2];
    #pragma unroll
    for (int i = 0; i < 4; i++) { acc[i][0] = make_float2(0.f,0.f); acc[i][1] = make_float2(0.f,0.f); }

    #pragma unroll 8
    for (int kk = 0; kk < 64; kk++) {
        float4 w4 = ((const float4*)w_sh)[kk*16 + tx];
        float2 i01 = *(const float2*)&in_T[kk*34 + ty*4];
        float2 i23 = *(const float2*)&in_T[kk*34 + ty*4 + 2];
        float iv[4] = {i01.x, i01.y, i23.x, i23.y};
        #pragma unroll
        for (int ri = 0; ri < 4; ri++) {
            float2 ib = make_float2(iv[ri], iv[ri]);
            acc[ri][0] = ffma2(make_float2(w4.x, w4.y), ib, acc[ri][0]);
            acc[ri][1] = ffma2(make_float2(w4.z, w4.w), ib, acc[ri][1]);
        }
    }

    float* outp = g_pp + (size_t)kh*NROWS*ATT_H + (size_t)(row0g + ty*4)*ATT_H + ch*64 + tx*4;
    #pragma unroll
    for (int ri = 0; ri < 4; ri++)
        *(float4*)(outp + (size_t)ri*ATT_H) =
            make_float4(acc[ri][0].x, acc[ri][0].y, acc[ri][1].x, acc[ri][1].y);
}

// ---------------- Kernel 1b: combine proj k-quarters + bias ----------------
__global__ void __launch_bounds__(256) proj_fix_kernel(
    const float* __restrict__ bkv, const float* __restrict__ bq)
{
    const int idx = blockIdx.x*256 + threadIdx.x;   // f4 index, NROWS*32 total
    const int row = idx >> 5;
    const int c4  = idx & 31;
    float4 s = make_float4(0.f,0.f,0.f,0.f);
    #pragma unroll
    for (int p = 0; p < 4; p++) {
        float4 a = ((const float4*)g_pp)[(size_t)p*NROWS*32 + idx];
        s.x += a.x; s.y += a.y; s.z += a.z; s.w += a.w;
    }
    const float* bias; float* out; int rloc;
    if (row < NB*NS) { bias = bkv; out = g_proj_kv; rloc = row; }
    else             { bias = bq;  out = g_proj_q;  rloc = row - NB*NS; }
    float4 bb = ((const float4*)bias)[c4];
    ((float4*)(out + (size_t)rloc*ATT_H))[c4] =
        make_float4(s.x+bb.x, s.y+bb.y, s.z+bb.z, s.w+bb.w);
}

// ---------------- Kernel 2: FUSED score + softmax + output GEMM ----------------
// Grid 128 (one per (b, 8q)). 384 threads:
//  warps 0-7 (256): E producers, thread tile 1q x 4s, MUFU-bound
//  warps 8-11 (128): O accumulators, 4q x 4h, kv via LDG (L2-hot), lag 1 chunk
#define CHS   128
#define NCH   (NS/CHS)          // 8
#define PKST  132               // pk row stride (floats)
#define PKBUF (CHS*PKST)        // 16896 floats
#define SM_FLOATS (2*PKBUF + 8*PKST + 128 + 2*CHS*8 + 64 + 8)

__global__ void __launch_bounds__(384) fused_kernel(
    const float* __restrict__ kv_g, const float* __restrict__ wv_g,
    const float* __restrict__ bv_g,
    float* __restrict__ out_o, float* __restrict__ out_w)
{
    extern __shared__ float sm[];
    float* pk_buf = sm;                    // 2 * 16896
    float* pq_sh  = pk_buf + 2*PKBUF;      // 8 * 132
    float* wv_sh  = pq_sh  + 8*PKST;       // 128
    float* E_ch   = wv_sh  + 128;          // 2 * 1024
    float* red    = E_ch   + 2*CHS*8;      // 64
    float* inv_sh = red    + 64;           // 8

    const int tid = threadIdx.x;
    const int bid = blockIdx.x;            // 128 = 2 b * 64 q-tiles
    const int b   = bid >> 6;
    const int q0  = (bid & 63) * 8;

    // pk chunk stage: 256 E-threads, 128 rows x 32 f4 (2 threads/row, 16 f4 each)
    #define ISSUE(c) { \
        int r = tid >> 1, o = (tid & 1) * 64; \
        const float* src = g_proj_kv + ((size_t)(b*NS) + (c)*CHS + r)*128 + o; \
        float* dst = pk_buf + ((c)&1)*PKBUF + r*PKST + o; \
        _Pragma("unroll") for (int j = 0; j < 16; j++) cp16(dst + j*4, src + j*4); }

    // prologue
    if (tid < 256) {
        int q = tid >> 5, a4 = tid & 31;
        *(float4*)(pq_sh + q*PKST + a4*4) =
            *(const float4*)(g_proj_q + (size_t)(b*NQ + q0 + q)*ATT_H + a4*4);
        ISSUE(0);
    } else if (tid < 288) {
        ((float4*)wv_sh)[tid - 256] = ((const float4*)wv_g)[tid - 256];
    }
    cp_commit();

    const float bv = __ldg(bv_g);
    const float LOG2E = 1.44269504f;

    // E identity: q = tid&7, sg = tid>>3 -> s = sg*4 + j
    const int lane = tid & 31;
    const int w    = tid >> 5;
    const int eq   = tid & 7;
    const int sg   = tid >> 3;     // 0..31 (valid for tid<256)
    float rsum = 0.f;

    // GEMM identity: 4q x 4h; tq = q-half, th = h-quad
    const int gt = tid - 256;
    const int tq = gt >> 6;
    const int th = gt & 63;
    float2 oacc[8];                // [qi][hp]
    #pragma unroll
    for (int i = 0; i < 8; i++) oacc[i] = make_float2(0.f, 0.f);

    const float* kvg = kv_g + (size_t)(b*NS)*KVH + th*4;

    #define GEMM_CHUNK(m) { \
        const float* kvb = kvg + (size_t)(m)*CHS*KVH; \
        const float* Eb  = E_ch + ((m)&1)*CHS*8 + tq*4; \
        for (int grp = 0; grp < CHS/8; grp++) { \
            float4 kvp[8], ep[8]; \
            _Pragma("unroll") for (int j = 0; j < 8; j++) \
                kvp[j] = *(const float4*)(kvb + (size_t)(grp*8 + j)*KVH); \
            _Pragma("unroll") for (int j = 0; j < 8; j++) \
                ep[j] = *(const float4*)(Eb + (grp*8 + j)*8); \
            _Pragma("unroll") for (int j = 0; j < 8; j++) { \
                float2 k0 = make_float2(kvp[j].x, kvp[j].y); \
                float2 k1 = make_float2(kvp[j].z, kvp[j].w); \
                float ev[4] = { ep[j].x, ep[j].y, ep[j].z, ep[j].w }; \
                _Pragma("unroll") for (int qi = 0; qi < 4; qi++) { \
                    float2 eb = make_float2(ev[qi], ev[qi]); \
                    oacc[qi*2    ] = ffma2(k0, eb, oacc[qi*2    ]); \
                    oacc[qi*2 + 1] = ffma2(k1, eb, oacc[qi*2 + 1]); \
                } \
            } \
        } }

    for (int c = 0; c < NCH; c++) {
        cp_wait0();
        __syncthreads();
        if (c + 1 < NCH && tid < 256) ISSUE(c + 1);
        cp_commit();

        if (tid < 256) {
            const float* pkb = pk_buf + (c&1)*PKBUF + (sg*4)*PKST;
            const float* pqb = pq_sh + eq*PKST;
            float a0 = 0.f, a1 = 0.f, a2 = 0.f, a3 = 0.f;
            #pragma unroll
            for (int a4 = 0; a4 < 32; a4++) {
                float4 pq = *(const float4*)(pqb + a4*4);
                float4 wv = ((const float4*)wv_sh)[a4];
                float4 p0 = *(const float4*)(pkb + 0*PKST + a4*4);
                float4 p1 = *(const float4*)(pkb + 1*PKST + a4*4);
                float4 p2 = *(const float4*)(pkb + 2*PKST + a4*4);
                float4 p3 = *(const float4*)(pkb + 3*PKST + a4*4);
                a0 += wv.x*fast_tanh(p0.x+pq.x) + wv.y*fast_tanh(p0.y+pq.y)
                    + wv.z*fast_tanh(p0.z+pq.z) + wv.w*fast_tanh(p0.w+pq.w);
                a1 += wv.x*fast_tanh(p1.x+pq.x) + wv.y*fast_tanh(p1.y+pq.y)
                    + wv.z*fast_tanh(p1.z+pq.z) + wv.w*fast_tanh(p1.w+pq.w);
                a2 += wv.x*fast_tanh(p2.x+pq.x) + wv.y*fast_tanh(p2.y+pq.y)
                    + wv.z*fast_tanh(p2.z+pq.z) + wv.w*fast_tanh(p2.w+pq.w);
                a3 += wv.x*fast_tanh(p3.x+pq.x) + wv.y*fast_tanh(p3.y+pq.y)
                    + wv.z*fast_tanh(p3.z+pq.z) + wv.w*fast_tanh(p3.w+pq.w);
            }
            float4 ev;
            ev.x = fast_ex2((a0 + bv) * LOG2E);
            ev.y = fast_ex2((a1 + bv) * LOG2E);
            ev.z = fast_ex2((a2 + bv) * LOG2E);
            ev.w = fast_ex2((a3 + bv) * LOG2E);
            rsum += (ev.x + ev.y) + (ev.z + ev.w);
            float* Eb = E_ch + (c&1)*CHS*8 + sg*32 + eq;
            Eb[0]  = ev.x;
            Eb[8]  = ev.y;
            Eb[16] = ev.z;
            Eb[24] = ev.w;
            *(float4*)(out_w + (size_t)(b*NQ + q0 + eq)*NS + c*CHS + sg*4) = ev;
        } else if (c > 0) {
            GEMM_CHUNK(c - 1);
        }
    }

    __syncthreads();
    if (tid >= 256) {
        GEMM_CHUNK(NCH - 1);
    } else {
        // reduce rsum over lanes sharing eq: {l, l^8, l^16, l^24}
        rsum += __shfl_xor_sync(0xffffffffu, rsum, 8);
        rsum += __shfl_xor_sync(0xffffffffu, rsum, 16);
        if (lane < 8) red[w*8 + lane] = rsum;
    }
    __syncthreads();
    if (tid < 8) {
        float s = 0.f;
        #pragma unroll
        for (int ww = 0; ww < 8; ww++) s += red[ww*8 + tid];
        inv_sh[tid] = 1.0f / s;
    }
    __syncthreads();

    // attention_output (normalized)
    if (tid >= 256) {
        #pragma unroll
        for (int qi = 0; qi < 4; qi++) {
            float inv = inv_sh[tq*4 + qi];
            *(float4*)(out_o + (size_t)(b*NQ + q0 + tq*4 + qi)*KVH + th*4) =
                make_float4(oacc[qi*2].x*inv, oacc[qi*2].y*inv,
                            oacc[qi*2+1].x*inv, oacc[qi*2+1].y*inv);
        }
    }
    // rescale this block's out_w rows in place (L2-hot)
    {
        float4* Wb = (float4*)(out_w + (size_t)(b*NQ + q0)*NS);
        for (int idx = tid; idx < 8*NS/4; idx += 384) {
            float inv = inv_sh[idx >> 8];
            float4 v = Wb[idx];
            v.x *= inv; v.y *= inv; v.z *= inv; v.w *= inv;
            Wb[idx] = v;
        }
    }
    #undef ISSUE
    #undef GEMM_CHUNK
}

extern "C" void kernel_launch(void* const* d_in, const int* in_sizes, int n_in,
                              void* d_out, int out_size)
{
    const float* kv  = (const float*)d_in[0];   // (2,1024,256)
    const float* qy  = (const float*)d_in[1];   // (2,512,256)
    const float* Wkv = (const float*)d_in[2];   // (256,128)
    const float* bkv = (const float*)d_in[3];   // (128)
    const float* Wq  = (const float*)d_in[4];   // (256,128)
    const float* bq  = (const float*)d_in[5];   // (128)
    const float* wv  = (const float*)d_in[6];   // (128)
    const float* bv  = (const float*)d_in[7];   // scalar

    float* out_o = (float*)d_out;               // attention_output: 2*512*256
    float* out_w = out_o + NB*NQ*KVH;           // attention_weight: 2*512*1024

    static int smem_set = 0;
    const int smem_bytes = SM_FLOATS * 4;
    if (!smem_set) {
        cudaFuncSetAttribute(fused_kernel, cudaFuncAttributeMaxDynamicSharedMemorySize, smem_bytes);
        smem_set = 1;
    }

    proj_kernel    <<<768, 128>>>(kv, qy, Wkv, Wq);
    proj_fix_kernel<<<384, 256>>>(bkv, bq);
    fused_kernel   <<<128, 384, smem_bytes>>>(kv, wv, bv, out_o, out_w);
}